// round 2
// baseline (speedup 1.0000x reference)
#include <cuda_runtime.h>
#include <cuda_bf16.h>

#define S_NUM 16384
#define D_DIM 256
#define NH 8

// ---- scratch (static device globals; no allocation) ----
__device__ int   g_starts[S_NUM + 1];
__device__ float g_pooled[(size_t)S_NUM * 256];
__device__ float g_q[(size_t)S_NUM * 256];
__device__ float g_a[(size_t)S_NUM * 2048];   // [S][8][256]
__device__ float g_pv[(size_t)S_NUM * 2048];  // [S][8][256]
__device__ float g_ps[(size_t)S_NUM * 256];

// ---- K0: segment start offsets via binary search (seg is sorted) ----
__global__ void starts_kernel(const int* __restrict__ seg, int N) {
    int s = blockIdx.x * blockDim.x + threadIdx.x;
    if (s > S_NUM) return;
    int lo = 0, hi = N;
    while (lo < hi) { int mid = (lo + hi) >> 1; if (seg[mid] < s) lo = mid + 1; else hi = mid; }
    g_starts[s] = lo;
}

// ---- K1: segment mean pool, block per sample, thread per dim ----
__global__ __launch_bounds__(256) void pool_kernel(const float* __restrict__ E) {
    int s = blockIdx.x, t = threadIdx.x;
    int s0 = g_starts[s], cnt = g_starts[s + 1] - s0;
    const float* p = E + (size_t)s0 * 256 + t;
    float a0 = 0.f, a1 = 0.f, a2 = 0.f, a3 = 0.f;
    int i = 0;
    for (; i + 4 <= cnt; i += 4) {
        a0 += p[(size_t)(i + 0) * 256];
        a1 += p[(size_t)(i + 1) * 256];
        a2 += p[(size_t)(i + 2) * 256];
        a3 += p[(size_t)(i + 3) * 256];
    }
    for (; i < cnt; i++) a0 += p[(size_t)i * 256];
    float inv = 1.0f / (float)(cnt > 1 ? cnt : 1);
    g_pooled[(size_t)s * 256 + t] = (a0 + a1 + a2 + a3) * inv;
}

// ---- generic fp32 SIMT GEMM: C = A*B (or A*B^T), 64x64 tile, beta=0 ----
// batched over blockIdx.z with element offsets aZ/bZ/cZ
__global__ __launch_bounds__(256) void gemm_kernel(
    const float* __restrict__ A, const float* __restrict__ B, float* __restrict__ C,
    int M, int N, int K, int lda, int ldb, int ldc,
    int aZ, int bZ, int cZ, int transB)
{
    A += (size_t)blockIdx.z * aZ;
    B += (size_t)blockIdx.z * bZ;
    C += (size_t)blockIdx.z * cZ;
    __shared__ float As[16][65];
    __shared__ float Bs[16][64];
    int bm = blockIdx.y * 64, bn = blockIdx.x * 64;
    int tid = threadIdx.x;
    int tx = tid & 15, ty = tid >> 4;
    float acc[4][4] = {};
    for (int k0 = 0; k0 < K; k0 += 16) {
        #pragma unroll
        for (int e = 0; e < 4; e++) {
            int f = tid + 256 * e;
            int m = f >> 4, kk = f & 15;
            float v = 0.f;
            int gm = bm + m, gk = k0 + kk;
            if (gm < M && gk < K) v = A[(size_t)gm * lda + gk];
            As[kk][m] = v;
        }
        #pragma unroll
        for (int e = 0; e < 4; e++) {
            int f = tid + 256 * e;
            int kk = f >> 6, n = f & 63;
            float v = 0.f;
            int gn = bn + n, gk = k0 + kk;
            if (gn < N && gk < K)
                v = transB ? B[(size_t)gn * ldb + gk] : B[(size_t)gk * ldb + gn];
            Bs[kk][n] = v;
        }
        __syncthreads();
        #pragma unroll
        for (int kk = 0; kk < 16; kk++) {
            float ar[4], br[4];
            #pragma unroll
            for (int i2 = 0; i2 < 4; i2++) ar[i2] = As[kk][ty * 4 + i2];
            #pragma unroll
            for (int j = 0; j < 4; j++) br[j] = Bs[kk][tx * 4 + j];
            #pragma unroll
            for (int i2 = 0; i2 < 4; i2++)
                #pragma unroll
                for (int j = 0; j < 4; j++)
                    acc[i2][j] = fmaf(ar[i2], br[j], acc[i2][j]);
        }
        __syncthreads();
    }
    #pragma unroll
    for (int i2 = 0; i2 < 4; i2++) {
        int m = bm + ty * 4 + i2;
        if (m >= M) continue;
        #pragma unroll
        for (int j = 0; j < 4; j++) {
            int n = bn + tx * 4 + j;
            if (n < N) C[(size_t)m * ldc + n] = acc[i2][j];
        }
    }
}

// ---- K4: fused scores + segment softmax + weighted value pooling ----
// block per sample; chunked online softmax (robust to any segment size)
__global__ __launch_bounds__(256) void attn_kernel(const float* __restrict__ E) {
    int s = blockIdx.x, t = threadIdx.x;
    int s0 = g_starts[s], cnt = g_starts[s + 1] - s0;

    __shared__ __align__(16) float a_sh[2048];      // a[s]: [h][d]
    __shared__ float e_sh[256 * 33];                // transposed e tile [d][i], pad 33
    __shared__ __align__(16) float w_sh[32 * 8];    // chunk scores -> exp weights [i][h]
    __shared__ float m_sh[8], l_sh[8], f_sh[8];

    const float* ap = g_a + (size_t)s * 2048;
    #pragma unroll
    for (int k = 0; k < 8; k++) a_sh[t + 256 * k] = ap[t + 256 * k];
    if (t < 8) { m_sh[t] = -1e30f; l_sh[t] = 0.f; f_sh[t] = 1.f; }
    float acc[8] = {0.f, 0.f, 0.f, 0.f, 0.f, 0.f, 0.f, 0.f};
    __syncthreads();

    int li = t & 31, lh = t >> 5;
    for (int base = 0; base < cnt; base += 32) {
        int c = min(32, cnt - base);
        // stage transposed tile (coalesced global reads)
        const float* ep = E + (size_t)(s0 + base) * 256 + t;
        for (int i = 0; i < c; i++)
            e_sh[t * 33 + i] = ep[(size_t)i * 256];
        __syncthreads();

        // scores: thread (i=li, h=lh) does the full 256-d dot from shared
        if (li < c) {
            const float* arow = a_sh + lh * 256;
            float sc = 0.f;
            #pragma unroll 8
            for (int d = 0; d < 256; d += 4) {
                float4 av = *(const float4*)(arow + d);
                sc = fmaf(av.x, e_sh[(d + 0) * 33 + li], sc);
                sc = fmaf(av.y, e_sh[(d + 1) * 33 + li], sc);
                sc = fmaf(av.z, e_sh[(d + 2) * 33 + li], sc);
                sc = fmaf(av.w, e_sh[(d + 3) * 33 + li], sc);
            }
            w_sh[li * 8 + lh] = sc * 0.17677669529663687f; // 1/sqrt(32)
        }
        __syncthreads();

        // online softmax state update (8 threads, one per head)
        if (t < 8) {
            float m_old = m_sh[t], m_new = m_old;
            for (int ii = 0; ii < c; ii++) m_new = fmaxf(m_new, w_sh[ii * 8 + t]);
            float f = __expf(m_old - m_new);
            float l = l_sh[t] * f;
            for (int ii = 0; ii < c; ii++) {
                float w = __expf(w_sh[ii * 8 + t] - m_new);
                w_sh[ii * 8 + t] = w;
                l += w;
            }
            m_sh[t] = m_new; l_sh[t] = l; f_sh[t] = f;
        }
        __syncthreads();

        // accumulate pooledV: thread owns dim d=t, 8 head accumulators
        #pragma unroll
        for (int h = 0; h < 8; h++) acc[h] *= f_sh[h];
        for (int ii = 0; ii < c; ii++) {
            float x = e_sh[t * 33 + ii];
            float4 p0 = *(const float4*)(w_sh + ii * 8);
            float4 p1 = *(const float4*)(w_sh + ii * 8 + 4);
            acc[0] = fmaf(p0.x, x, acc[0]);
            acc[1] = fmaf(p0.y, x, acc[1]);
            acc[2] = fmaf(p0.z, x, acc[2]);
            acc[3] = fmaf(p0.w, x, acc[3]);
            acc[4] = fmaf(p1.x, x, acc[4]);
            acc[5] = fmaf(p1.y, x, acc[5]);
            acc[6] = fmaf(p1.z, x, acc[6]);
            acc[7] = fmaf(p1.w, x, acc[7]);
        }
        __syncthreads();
    }

    float* outp = g_pv + (size_t)s * 2048;
    #pragma unroll
    for (int h = 0; h < 8; h++) {
        float l = l_sh[h];
        outp[h * 256 + t] = (l > 0.f) ? acc[h] / l : 0.f;
    }
}

extern "C" void kernel_launch(void* const* d_in, const int* in_sizes, int n_in,
                              void* d_out, int out_size)
{
    const float* E   = (const float*)d_in[0];
    const int*   seg = (const int*)d_in[1];
    // num_samples may (or may not) be passed as a scalar input at index 2
    int wi = 2;
    if (n_in >= 7 && in_sizes[2] != 256 * 256) wi = 3;
    const float* Wq = (const float*)d_in[wi + 0];
    const float* Wk = (const float*)d_in[wi + 1];
    const float* Wv = (const float*)d_in[wi + 2];
    const float* Wo = (const float*)d_in[wi + 3];
    int N = in_sizes[0] / 256;
    float* out = (float*)d_out;

    float *pooled, *q, *a, *pv, *ps;
    cudaGetSymbolAddress((void**)&pooled, g_pooled);
    cudaGetSymbolAddress((void**)&q, g_q);
    cudaGetSymbolAddress((void**)&a, g_a);
    cudaGetSymbolAddress((void**)&pv, g_pv);
    cudaGetSymbolAddress((void**)&ps, g_ps);

    // K0: segment boundaries
    starts_kernel<<<(S_NUM + 1 + 255) / 256, 256>>>(seg, N);
    // K1: mean pool -> g_pooled [S,256]
    pool_kernel<<<S_NUM, 256>>>(E);
    // K2: q = pooled @ Wq                       [S,256]x[256,256]
    gemm_kernel<<<dim3(4, 256, 1), 256>>>(pooled, Wq, q,
        S_NUM, 256, 256, 256, 256, 256, 0, 0, 0, 0);
    // K3: a[:,h,:] = q[:,h-block] @ Wk[:,h-block]^T   (8 GEMMs, K=32)
    gemm_kernel<<<dim3(4, 256, 8), 256>>>(q, Wk, a,
        S_NUM, 256, 32, 256, 256, 2048, 32, 32, 256, 1);
    // K4: fused scores + segment softmax + weighted pooling -> g_pv
    attn_kernel<<<S_NUM, 256>>>(E);
    // K5a: per_sample[:,h-block] = pv[:,h,:] @ Wv[:,h-block]  (8 GEMMs, N=32)
    gemm_kernel<<<dim3(1, 256, 8), 256>>>(pv, Wv, ps,
        S_NUM, 32, 256, 2048, 256, 256, 256, 32, 32, 0);
    // K5b: out = per_sample @ Wo
    gemm_kernel<<<dim3(4, 256, 1), 256>>>(ps, Wo, out,
        S_NUM, 256, 256, 256, 256, 256, 0, 0, 0, 0);
}

// round 4
// speedup vs baseline: 1.4567x; 1.4567x over previous
#include <cuda_runtime.h>
#include <cuda_bf16.h>

#define S_NUM 16384

// ---- scratch (static device globals; no allocation) ----
__device__ int   g_starts[S_NUM + 1];
__device__ float g_pooled[(size_t)S_NUM * 256];
__device__ float g_q[(size_t)S_NUM * 256];
__device__ float g_a[(size_t)S_NUM * 2048];   // [S][8][256]
__device__ float g_pv[(size_t)S_NUM * 2048];  // [S][8][256]
__device__ float g_ps[(size_t)S_NUM * 256];

// ---- packed f32x2 helpers (sm_103a FFMA2 path, PTX-only) ----
__device__ __forceinline__ unsigned long long pk2(float x, float y) {
    unsigned long long r;
    asm("mov.b64 %0,{%1,%2};" : "=l"(r) : "f"(x), "f"(y));
    return r;
}
__device__ __forceinline__ void upk2(unsigned long long v, float& x, float& y) {
    asm("mov.b64 {%0,%1},%2;" : "=f"(x), "=f"(y) : "l"(v));
}
__device__ __forceinline__ unsigned long long ffma2(unsigned long long a,
                                                    unsigned long long b,
                                                    unsigned long long c) {
    unsigned long long d;
    asm("fma.rn.f32x2 %0,%1,%2,%3;" : "=l"(d) : "l"(a), "l"(b), "l"(c));
    return d;
}
__device__ __forceinline__ unsigned long long fmul2(unsigned long long a,
                                                    unsigned long long b) {
    unsigned long long d;
    asm("mul.rn.f32x2 %0,%1,%2;" : "=l"(d) : "l"(a), "l"(b));
    return d;
}

// ---- K0: segment start offsets via binary search (seg is sorted) ----
__global__ void starts_kernel(const int* __restrict__ seg, int N) {
    int s = blockIdx.x * blockDim.x + threadIdx.x;
    if (s > S_NUM) return;
    int lo = 0, hi = N;
    while (lo < hi) { int mid = (lo + hi) >> 1; if (seg[mid] < s) lo = mid + 1; else hi = mid; }
    g_starts[s] = lo;
}

// ---- K1: segment mean pool, block per sample, thread per dim ----
__global__ __launch_bounds__(256) void pool_kernel(const float* __restrict__ E) {
    int s = blockIdx.x, t = threadIdx.x;
    int s0 = g_starts[s], cnt = g_starts[s + 1] - s0;
    const float* p = E + (size_t)s0 * 256 + t;
    float a0 = 0.f, a1 = 0.f, a2 = 0.f, a3 = 0.f;
    float a4 = 0.f, a5 = 0.f, a6 = 0.f, a7 = 0.f;
    int i = 0;
    for (; i + 8 <= cnt; i += 8) {
        a0 += p[(size_t)(i + 0) * 256];
        a1 += p[(size_t)(i + 1) * 256];
        a2 += p[(size_t)(i + 2) * 256];
        a3 += p[(size_t)(i + 3) * 256];
        a4 += p[(size_t)(i + 4) * 256];
        a5 += p[(size_t)(i + 5) * 256];
        a6 += p[(size_t)(i + 6) * 256];
        a7 += p[(size_t)(i + 7) * 256];
    }
    for (; i < cnt; i++) a0 += p[(size_t)i * 256];
    float inv = 1.0f / (float)(cnt > 1 ? cnt : 1);
    g_pooled[(size_t)s * 256 + t] = ((a0 + a1) + (a2 + a3) + (a4 + a5) + (a6 + a7)) * inv;
}

// ---- specialized fp32 GEMM, TM=128 x TN, TK=16, FFMA2 accumulation ----
// no bounds checks: M % 128 == 0, N % TN == 0, K % 16 == 0 guaranteed.
template<int TN, bool TRANSB>
__global__ __launch_bounds__(256) void gemm_t(
    const float* __restrict__ A, const float* __restrict__ B, float* __restrict__ C,
    int K, int lda, int ldb, int ldc, int aZ, int bZ, int cZ)
{
    constexpr int TX = TN / 4;   // threads across n (16 or 8)
    constexpr int RM = TX / 2;   // rows per thread (8 or 4)
    A += (size_t)blockIdx.z * aZ + (size_t)blockIdx.y * 128 * lda;
    B += (size_t)blockIdx.z * bZ;
    C += (size_t)blockIdx.z * cZ + (size_t)blockIdx.y * 128 * ldc + blockIdx.x * TN;
    const int bn = blockIdx.x * TN;

    __shared__ __align__(16) float As[16][132];
    __shared__ __align__(16) float Bs[16][TN + 4];

    int tid = threadIdx.x;
    int tx = tid % TX, ty = tid / TX;
    unsigned long long acc2[RM][2];
    #pragma unroll
    for (int i = 0; i < RM; i++) { acc2[i][0] = 0ull; acc2[i][1] = 0ull; }

    for (int k0 = 0; k0 < K; k0 += 16) {
        // A tile: 128x16 = 512 float4, 2 per thread
        #pragma unroll
        for (int e = 0; e < 2; e++) {
            int idx = tid + 256 * e;
            int m = idx >> 2, kc = idx & 3;
            float4 v = *(const float4*)(A + (size_t)m * lda + k0 + kc * 4);
            As[kc * 4 + 0][m] = v.x; As[kc * 4 + 1][m] = v.y;
            As[kc * 4 + 2][m] = v.z; As[kc * 4 + 3][m] = v.w;
        }
        // B tile
        if (!TRANSB) {
            constexpr int NB4 = 4 * TN;   // float4 count (256 or 128)
            int idx = tid;
            if (NB4 == 256 || idx < NB4) {
                int kk = idx / (TN / 4), nc = idx % (TN / 4);
                float4 v = *(const float4*)(B + (size_t)(k0 + kk) * ldb + bn + nc * 4);
                *(float4*)&Bs[kk][nc * 4] = v;
            }
        } else {
            constexpr int NB4 = 4 * TN;
            int idx = tid;
            if (NB4 == 256 || idx < NB4) {
                int n = idx >> 2, kc = idx & 3;
                float4 v = *(const float4*)(B + (size_t)(bn + n) * ldb + k0 + kc * 4);
                Bs[kc * 4 + 0][n] = v.x; Bs[kc * 4 + 1][n] = v.y;
                Bs[kc * 4 + 2][n] = v.z; Bs[kc * 4 + 3][n] = v.w;
            }
        }
        __syncthreads();
        #pragma unroll
        for (int kk = 0; kk < 16; kk++) {
            ulonglong2 bv = *(const ulonglong2*)&Bs[kk][tx * 4];
            #pragma unroll
            for (int i = 0; i < RM; i += 4) {
                float4 a4 = *(const float4*)&As[kk][ty * RM + i];
                unsigned long long aa;
                aa = pk2(a4.x, a4.x);
                acc2[i + 0][0] = ffma2(aa, bv.x, acc2[i + 0][0]);
                acc2[i + 0][1] = ffma2(aa, bv.y, acc2[i + 0][1]);
                aa = pk2(a4.y, a4.y);
                acc2[i + 1][0] = ffma2(aa, bv.x, acc2[i + 1][0]);
                acc2[i + 1][1] = ffma2(aa, bv.y, acc2[i + 1][1]);
                aa = pk2(a4.z, a4.z);
                acc2[i + 2][0] = ffma2(aa, bv.x, acc2[i + 2][0]);
                acc2[i + 2][1] = ffma2(aa, bv.y, acc2[i + 2][1]);
                aa = pk2(a4.w, a4.w);
                acc2[i + 3][0] = ffma2(aa, bv.x, acc2[i + 3][0]);
                acc2[i + 3][1] = ffma2(aa, bv.y, acc2[i + 3][1]);
            }
        }
        __syncthreads();
    }
    #pragma unroll
    for (int i = 0; i < RM; i++) {
        float4 v;
        upk2(acc2[i][0], v.x, v.y);
        upk2(acc2[i][1], v.z, v.w);
        *(float4*)(C + (size_t)(ty * RM + i) * ldc + tx * 4) = v;
    }
}

// ---- K4: fused scores + segment softmax + weighted value pooling ----
__global__ __launch_bounds__(256) void attn_kernel(const float* __restrict__ E) {
    int s = blockIdx.x, t = threadIdx.x;
    int s0 = g_starts[s], cnt = g_starts[s + 1] - s0;

    __shared__ __align__(16) float a_sh[2048];       // a[s]: [h][d]
    __shared__ __align__(16) float e_sh[32][260];    // [i][d], 4-float pad
    __shared__ __align__(16) float w_sh[32 * 8];     // chunk weights [i][h]
    __shared__ __align__(16) float m_sh[8];
    __shared__ __align__(16) float l_sh[8];
    __shared__ __align__(16) float f_sh[8];

    const float* ap = g_a + (size_t)s * 2048;
    #pragma unroll
    for (int k = 0; k < 8; k++) a_sh[t + 256 * k] = ap[t + 256 * k];
    if (t < 8) { m_sh[t] = -1e30f; l_sh[t] = 0.f; f_sh[t] = 1.f; }
    unsigned long long acc2[4] = {0ull, 0ull, 0ull, 0ull};
    __syncthreads();

    int li = t & 31, lh = t >> 5;
    for (int base = 0; base < cnt; base += 32) {
        int c = min(32, cnt - base);
        // stage tile [i][d] with batched loads (MLP=8)
        const float* ep = E + (size_t)(s0 + base) * 256 + t;
        #pragma unroll
        for (int g = 0; g < 32; g += 8) {
            float v[8];
            #pragma unroll
            for (int j = 0; j < 8; j++)
                v[j] = (g + j < c) ? ep[(size_t)(g + j) * 256] : 0.f;
            #pragma unroll
            for (int j = 0; j < 8; j++) e_sh[g + j][t] = v[j];
        }
        __syncthreads();

        // scores: thread (i=li, h=lh), FFMA2 dot over 256 dims
        if (li < c) {
            const ulonglong2* er = (const ulonglong2*)&e_sh[li][0];
            const ulonglong2* ar = (const ulonglong2*)(a_sh + (lh << 8));
            unsigned long long s2a = 0ull, s2b = 0ull;
            #pragma unroll
            for (int d = 0; d < 64; d++) {
                ulonglong2 ev = er[d];
                ulonglong2 av = ar[d];
                s2a = ffma2(av.x, ev.x, s2a);
                s2b = ffma2(av.y, ev.y, s2b);
            }
            float x0, x1, y0, y1;
            upk2(s2a, x0, x1); upk2(s2b, y0, y1);
            w_sh[li * 8 + lh] = ((x0 + x1) + (y0 + y1)) * 0.17677669529663687f;
        }
        __syncthreads();

        // online softmax state update (8 threads, one per head)
        if (t < 8) {
            float m_old = m_sh[t], m_new = m_old;
            for (int ii = 0; ii < c; ii++) m_new = fmaxf(m_new, w_sh[ii * 8 + t]);
            float f = __expf(m_old - m_new);
            float l = l_sh[t] * f;
            for (int ii = 0; ii < c; ii++) {
                float w = __expf(w_sh[ii * 8 + t] - m_new);
                w_sh[ii * 8 + t] = w;
                l += w;
            }
            m_sh[t] = m_new; l_sh[t] = l; f_sh[t] = f;
        }
        __syncthreads();

        // pooledV accumulate: thread owns dim d=t, 8 head accumulators (packed)
        const unsigned long long* fp = (const unsigned long long*)f_sh;
        #pragma unroll
        for (int j = 0; j < 4; j++) acc2[j] = fmul2(acc2[j], fp[j]);
        for (int ii = 0; ii < c; ii++) {
            float x = e_sh[ii][t];
            unsigned long long xx = pk2(x, x);
            ulonglong2 w01 = *(const ulonglong2*)(w_sh + ii * 8);
            ulonglong2 w23 = *(const ulonglong2*)(w_sh + ii * 8 + 4);
            acc2[0] = ffma2(w01.x, xx, acc2[0]);
            acc2[1] = ffma2(w01.y, xx, acc2[1]);
            acc2[2] = ffma2(w23.x, xx, acc2[2]);
            acc2[3] = ffma2(w23.y, xx, acc2[3]);
        }
        __syncthreads();
    }

    float* outp = g_pv + (size_t)s * 2048;
    #pragma unroll
    for (int j = 0; j < 4; j++) {
        float v0, v1;
        upk2(acc2[j], v0, v1);
        float l0 = l_sh[2 * j], l1 = l_sh[2 * j + 1];
        outp[(2 * j) * 256 + t]     = (l0 > 0.f) ? v0 / l0 : 0.f;
        outp[(2 * j + 1) * 256 + t] = (l1 > 0.f) ? v1 / l1 : 0.f;
    }
}

extern "C" void kernel_launch(void* const* d_in, const int* in_sizes, int n_in,
                              void* d_out, int out_size)
{
    const float* E   = (const float*)d_in[0];
    const int*   seg = (const int*)d_in[1];
    int wi = 2;
    if (n_in >= 7 && in_sizes[2] != 256 * 256) wi = 3;
    const float* Wq = (const float*)d_in[wi + 0];
    const float* Wk = (const float*)d_in[wi + 1];
    const float* Wv = (const float*)d_in[wi + 2];
    const float* Wo = (const float*)d_in[wi + 3];
    int N = in_sizes[0] / 256;
    float* out = (float*)d_out;

    float *pooled, *q, *a, *pv, *ps;
    cudaGetSymbolAddress((void**)&pooled, g_pooled);
    cudaGetSymbolAddress((void**)&q, g_q);
    cudaGetSymbolAddress((void**)&a, g_a);
    cudaGetSymbolAddress((void**)&pv, g_pv);
    cudaGetSymbolAddress((void**)&ps, g_ps);

    // K0: segment boundaries
    starts_kernel<<<(S_NUM + 1 + 255) / 256, 256>>>(seg, N);
    // K1: mean pool -> g_pooled [S,256]
    pool_kernel<<<S_NUM, 256>>>(E);
    // K2: q = pooled @ Wq
    gemm_t<64, false><<<dim3(4, 128, 1), 256>>>(pooled, Wq, q,
        256, 256, 256, 256, 0, 0, 0);
    // K3: a[:,h,:] = q[:,hb] @ Wk[:,hb]^T   (batched over heads, K=32)
    gemm_t<64, true><<<dim3(4, 128, 8), 256>>>(q, Wk, a,
        32, 256, 256, 2048, 32, 32, 256);
    // K4: fused scores + segment softmax + weighted pooling -> g_pv
    attn_kernel<<<S_NUM, 256>>>(E);
    // K5a: ps[:,hb] = pv[:,h,:] @ Wv[:,hb]  (batched over heads, N=32)
    gemm_t<32, false><<<dim3(1, 128, 8), 256>>>(pv, Wv, ps,
        256, 2048, 256, 256, 256, 32, 32);
    // K5b: out = ps @ Wo
    gemm_t<64, false><<<dim3(4, 128, 1), 256>>>(ps, Wo, out,
        256, 256, 256, 256, 0, 0, 0);
}

// round 5
// speedup vs baseline: 1.4690x; 1.0085x over previous
#include <cuda_runtime.h>
#include <cuda_bf16.h>

#define S_NUM 16384

// ---- scratch (static device globals; no allocation) ----
__device__ int   g_starts[S_NUM + 1];
__device__ float g_pooled[(size_t)S_NUM * 256];
__device__ float g_q[(size_t)S_NUM * 256];
__device__ float g_a[(size_t)S_NUM * 2048];   // [S][8][256]
__device__ float g_pv[(size_t)S_NUM * 2048];  // [S][8][256]
__device__ float g_ps[(size_t)S_NUM * 256];

// ---- packed f32x2 helpers (sm_103a FFMA2 path, PTX-only) ----
__device__ __forceinline__ unsigned long long pk2(float x, float y) {
    unsigned long long r;
    asm("mov.b64 %0,{%1,%2};" : "=l"(r) : "f"(x), "f"(y));
    return r;
}
__device__ __forceinline__ void upk2(unsigned long long v, float& x, float& y) {
    asm("mov.b64 {%0,%1},%2;" : "=f"(x), "=f"(y) : "l"(v));
}
__device__ __forceinline__ unsigned long long ffma2(unsigned long long a,
                                                    unsigned long long b,
                                                    unsigned long long c) {
    unsigned long long d;
    asm("fma.rn.f32x2 %0,%1,%2,%3;" : "=l"(d) : "l"(a), "l"(b), "l"(c));
    return d;
}
__device__ __forceinline__ unsigned long long fmul2(unsigned long long a,
                                                    unsigned long long b) {
    unsigned long long d;
    asm("mul.rn.f32x2 %0,%1,%2;" : "=l"(d) : "l"(a), "l"(b));
    return d;
}

// ---- K0: segment start offsets via binary search (seg is sorted) ----
__global__ void starts_kernel(const int* __restrict__ seg, int N) {
    int s = blockIdx.x * blockDim.x + threadIdx.x;
    if (s > S_NUM) return;
    int lo = 0, hi = N;
    while (lo < hi) { int mid = (lo + hi) >> 1; if (seg[mid] < s) lo = mid + 1; else hi = mid; }
    g_starts[s] = lo;
}

// ---- K1: segment mean pool, block per sample, thread per dim ----
__global__ __launch_bounds__(256) void pool_kernel(const float* __restrict__ E) {
    int s = blockIdx.x, t = threadIdx.x;
    int s0 = g_starts[s], cnt = g_starts[s + 1] - s0;
    const float* p = E + (size_t)s0 * 256 + t;
    float a0 = 0.f, a1 = 0.f, a2 = 0.f, a3 = 0.f;
    float a4 = 0.f, a5 = 0.f, a6 = 0.f, a7 = 0.f;
    int i = 0;
    for (; i + 8 <= cnt; i += 8) {
        a0 += p[(size_t)(i + 0) * 256];
        a1 += p[(size_t)(i + 1) * 256];
        a2 += p[(size_t)(i + 2) * 256];
        a3 += p[(size_t)(i + 3) * 256];
        a4 += p[(size_t)(i + 4) * 256];
        a5 += p[(size_t)(i + 5) * 256];
        a6 += p[(size_t)(i + 6) * 256];
        a7 += p[(size_t)(i + 7) * 256];
    }
    for (; i < cnt; i++) a0 += p[(size_t)i * 256];
    float inv = 1.0f / (float)(cnt > 1 ? cnt : 1);
    g_pooled[(size_t)s * 256 + t] = ((a0 + a1) + (a2 + a3) + (a4 + a5) + (a6 + a7)) * inv;
}

// ---- specialized fp32 GEMM, 128 x TN tile, TK=16, FFMA2, double-buffered ----
// no bounds checks: M % 128 == 0, N % TN == 0, K % 16 == 0 guaranteed.
template<int TN, bool TRANSB>
__global__ __launch_bounds__(256) void gemm_t(
    const float* __restrict__ A, const float* __restrict__ B, float* __restrict__ C,
    int K, int lda, int ldb, int ldc, int aZ, int bZ, int cZ)
{
    constexpr int TX = TN / 4;   // threads across n (16 or 8)
    constexpr int RM = TX / 2;   // rows per thread (8 or 4)
    A += (size_t)blockIdx.z * aZ + (size_t)blockIdx.y * 128 * lda;
    B += (size_t)blockIdx.z * bZ;
    C += (size_t)blockIdx.z * cZ + (size_t)blockIdx.y * 128 * ldc + blockIdx.x * TN;
    const int bn = blockIdx.x * TN;

    __shared__ __align__(16) float As[2][16][132];
    __shared__ __align__(16) float Bs[2][16][TN + 4];

    const int tid = threadIdx.x;
    const int tx = tid % TX, ty = tid / TX;
    // A-load role: rows am, am+64, k-chunk akc
    const int am = tid >> 2, akc = tid & 3;
    // B-load roles
    const int bkk = (!TRANSB) ? (tid / (TX)) : 0;      // !TRANSB: k row
    const int bnc = (!TRANSB) ? (tid % (TX)) : 0;      // !TRANSB: n chunk
    const int btn = TRANSB ? (tid >> 2) : 0;           // TRANSB: n row
    const int btk = TRANSB ? (tid & 3) : 0;            // TRANSB: k chunk
    const bool bpred = (4 * TN == 256) || (tid < 4 * TN);

    unsigned long long acc2[RM][2];
    #pragma unroll
    for (int i = 0; i < RM; i++) { acc2[i][0] = 0ull; acc2[i][1] = 0ull; }

    float4 ra0, ra1, rb;

    auto ldg = [&](int k0) {
        ra0 = *(const float4*)(A + (size_t)am * lda + k0 + akc * 4);
        ra1 = *(const float4*)(A + (size_t)(am + 64) * lda + k0 + akc * 4);
        if (bpred) {
            if (!TRANSB)
                rb = *(const float4*)(B + (size_t)(k0 + bkk) * ldb + bn + bnc * 4);
            else
                rb = *(const float4*)(B + (size_t)(bn + btn) * ldb + k0 + btk * 4);
        }
    };
    auto sts = [&](int p) {
        As[p][akc * 4 + 0][am] = ra0.x; As[p][akc * 4 + 1][am] = ra0.y;
        As[p][akc * 4 + 2][am] = ra0.z; As[p][akc * 4 + 3][am] = ra0.w;
        As[p][akc * 4 + 0][am + 64] = ra1.x; As[p][akc * 4 + 1][am + 64] = ra1.y;
        As[p][akc * 4 + 2][am + 64] = ra1.z; As[p][akc * 4 + 3][am + 64] = ra1.w;
        if (bpred) {
            if (!TRANSB) {
                *(float4*)&Bs[p][bkk][bnc * 4] = rb;
            } else {
                Bs[p][btk * 4 + 0][btn] = rb.x; Bs[p][btk * 4 + 1][btn] = rb.y;
                Bs[p][btk * 4 + 2][btn] = rb.z; Bs[p][btk * 4 + 3][btn] = rb.w;
            }
        }
    };
    auto compute = [&](int p) {
        #pragma unroll
        for (int kk = 0; kk < 16; kk++) {
            ulonglong2 bv = *(const ulonglong2*)&Bs[p][kk][tx * 4];
            #pragma unroll
            for (int i = 0; i < RM; i += 4) {
                float4 a4 = *(const float4*)&As[p][kk][ty * RM + i];
                unsigned long long aa;
                aa = pk2(a4.x, a4.x);
                acc2[i + 0][0] = ffma2(aa, bv.x, acc2[i + 0][0]);
                acc2[i + 0][1] = ffma2(aa, bv.y, acc2[i + 0][1]);
                aa = pk2(a4.y, a4.y);
                acc2[i + 1][0] = ffma2(aa, bv.x, acc2[i + 1][0]);
                acc2[i + 1][1] = ffma2(aa, bv.y, acc2[i + 1][1]);
                aa = pk2(a4.z, a4.z);
                acc2[i + 2][0] = ffma2(aa, bv.x, acc2[i + 2][0]);
                acc2[i + 2][1] = ffma2(aa, bv.y, acc2[i + 2][1]);
                aa = pk2(a4.w, a4.w);
                acc2[i + 3][0] = ffma2(aa, bv.x, acc2[i + 3][0]);
                acc2[i + 3][1] = ffma2(aa, bv.y, acc2[i + 3][1]);
            }
        }
    };

    const int T = K >> 4;
    ldg(0);
    sts(0);
    __syncthreads();
    for (int kt = 1; kt < T; kt++) {
        ldg(kt * 16);
        compute((kt - 1) & 1);
        sts(kt & 1);
        __syncthreads();
    }
    compute((T - 1) & 1);

    #pragma unroll
    for (int i = 0; i < RM; i++) {
        float4 v;
        upk2(acc2[i][0], v.x, v.y);
        upk2(acc2[i][1], v.z, v.w);
        *(float4*)(C + (size_t)(ty * RM + i) * ldc + tx * 4) = v;
    }
}

// ---- K4: fused scores + segment softmax + weighted value pooling ----
// block per sample; score phase uses broadcast-friendly lane layout:
// lane l -> element i = warp*4 + (l>>3), head h = l&7.
#define EP 264   // e row stride (264 % 32 == 8 -> conflict-free 16B row chunks)
__global__ __launch_bounds__(256) void attn_kernel(const float* __restrict__ E) {
    int s = blockIdx.x, t = threadIdx.x;
    int s0 = g_starts[s], cnt = g_starts[s + 1] - s0;

    __shared__ __align__(16) float e_sh[32 * EP];   // [i][d]
    __shared__ __align__(16) float a_sc[2048];      // xor-swizzled [d4][h] float4
    __shared__ __align__(16) float w_sh[8 * 36];    // [h][i]
    __shared__ __align__(16) float wT_sh[32 * 8];   // [i][h]
    __shared__ __align__(16) float m_sh[8];
    __shared__ __align__(16) float l_sh[8];
    __shared__ __align__(16) float f_sh[8];

    // stage a (once per segment): coalesced LDG, xor-swizzled conflict-free STS.
    // logical float4 cell (d4, h) lives at float4-index (d4*8 + h) ^ (d4 & 7)
    const float* ap = g_a + (size_t)s * 2048;
    {
        int d4 = t >> 2, j = t & 3;
        int sw = (d4 & 7);
        #pragma unroll
        for (int k = 0; k < 8; k++) {           // k = head
            float v = ap[k * 256 + t];          // a[h=k][d=t]
            int f4 = (d4 * 8 + k) ^ sw;
            a_sc[f4 * 4 + j] = v;
        }
    }
    if (t < 8) { m_sh[t] = -1e30f; l_sh[t] = 0.f; f_sh[t] = 1.f; }
    unsigned long long acc2[4] = {0ull, 0ull, 0ull, 0ull};

    const int w = t >> 5, l = t & 31;
    const int il = l >> 3, hh = l & 7;
    const int si = w * 4 + il;                   // score element index
    __syncthreads();

    for (int base = 0; base < cnt; base += 32) {
        int c = min(32, cnt - base);
        // stage e tile [i][d] (zero-fill i >= c), coalesced, MLP=8
        const float* ep = E + (size_t)(s0 + base) * 256 + t;
        #pragma unroll
        for (int g = 0; g < 32; g += 8) {
            float v[8];
            #pragma unroll
            for (int j = 0; j < 8; j++)
                v[j] = (g + j < c) ? ep[(size_t)(g + j) * 256] : 0.f;
            #pragma unroll
            for (int j = 0; j < 8; j++) e_sh[(g + j) * EP + t] = v[j];
        }
        __syncthreads();

        // scores: lane computes score(si, hh); e reads broadcast x8, a x4
        {
            const ulonglong2* err = (const ulonglong2*)(e_sh + si * EP);
            const ulonglong2* arr = (const ulonglong2*)a_sc;
            unsigned long long sa = 0ull, sb = 0ull;
            #pragma unroll
            for (int d4 = 0; d4 < 64; d4++) {
                ulonglong2 ev = err[d4];
                ulonglong2 av = arr[(d4 * 8 + hh) ^ (d4 & 7)];
                sa = ffma2(ev.x, av.x, sa);
                sb = ffma2(ev.y, av.y, sb);
            }
            float x0, x1, y0, y1;
            upk2(sa, x0, x1); upk2(sb, y0, y1);
            w_sh[hh * 36 + si] = ((x0 + x1) + (y0 + y1)) * 0.17677669529663687f;
        }
        __syncthreads();

        // softmax: warp w owns head w; warp-parallel max/exp/sum
        {
            float sc = (l < c) ? w_sh[w * 36 + l] : -1e30f;
            float mx = sc;
            #pragma unroll
            for (int o = 16; o; o >>= 1) mx = fmaxf(mx, __shfl_xor_sync(0xffffffffu, mx, o));
            float m_old = m_sh[w];
            float m_new = fmaxf(m_old, mx);
            float ex = __expf(sc - m_new);
            float sum = ex;
            #pragma unroll
            for (int o = 16; o; o >>= 1) sum += __shfl_xor_sync(0xffffffffu, sum, o);
            wT_sh[l * 8 + w] = ex;
            if (l == 0) {
                float f = __expf(m_old - m_new);
                f_sh[w] = f;
                l_sh[w] = l_sh[w] * f + sum;
                m_sh[w] = m_new;
            }
        }
        __syncthreads();

        // pooledV accumulate: thread owns dim d=t, 8 packed head accumulators
        const unsigned long long* fp = (const unsigned long long*)f_sh;
        #pragma unroll
        for (int j = 0; j < 4; j++) acc2[j] = fmul2(acc2[j], fp[j]);
        for (int ii = 0; ii < c; ii++) {
            float x = e_sh[ii * EP + t];
            unsigned long long xx = pk2(x, x);
            ulonglong2 w01 = *(const ulonglong2*)(wT_sh + ii * 8);
            ulonglong2 w23 = *(const ulonglong2*)(wT_sh + ii * 8 + 4);
            acc2[0] = ffma2(w01.x, xx, acc2[0]);
            acc2[1] = ffma2(w01.y, xx, acc2[1]);
            acc2[2] = ffma2(w23.x, xx, acc2[2]);
            acc2[3] = ffma2(w23.y, xx, acc2[3]);
        }
        __syncthreads();
    }

    float* outp = g_pv + (size_t)s * 2048;
    #pragma unroll
    for (int j = 0; j < 4; j++) {
        float v0, v1;
        upk2(acc2[j], v0, v1);
        float l0 = l_sh[2 * j], l1 = l_sh[2 * j + 1];
        outp[(2 * j) * 256 + t]     = (l0 > 0.f) ? v0 / l0 : 0.f;
        outp[(2 * j + 1) * 256 + t] = (l1 > 0.f) ? v1 / l1 : 0.f;
    }
}

extern "C" void kernel_launch(void* const* d_in, const int* in_sizes, int n_in,
                              void* d_out, int out_size)
{
    const float* E   = (const float*)d_in[0];
    const int*   seg = (const int*)d_in[1];
    int wi = 2;
    if (n_in >= 7 && in_sizes[2] != 256 * 256) wi = 3;
    const float* Wq = (const float*)d_in[wi + 0];
    const float* Wk = (const float*)d_in[wi + 1];
    const float* Wv = (const float*)d_in[wi + 2];
    const float* Wo = (const float*)d_in[wi + 3];
    int N = in_sizes[0] / 256;
    float* out = (float*)d_out;

    float *pooled, *q, *a, *pv, *ps;
    cudaGetSymbolAddress((void**)&pooled, g_pooled);
    cudaGetSymbolAddress((void**)&q, g_q);
    cudaGetSymbolAddress((void**)&a, g_a);
    cudaGetSymbolAddress((void**)&pv, g_pv);
    cudaGetSymbolAddress((void**)&ps, g_ps);

    // K0: segment boundaries
    starts_kernel<<<(S_NUM + 1 + 255) / 256, 256>>>(seg, N);
    // K1: mean pool -> g_pooled [S,256]
    pool_kernel<<<S_NUM, 256>>>(E);
    // K2: q = pooled @ Wq
    gemm_t<64, false><<<dim3(4, 128, 1), 256>>>(pooled, Wq, q,
        256, 256, 256, 256, 0, 0, 0);
    // K3: a[:,h,:] = q[:,hb] @ Wk[:,hb]^T   (batched over heads, K=32)
    gemm_t<64, true><<<dim3(4, 128, 8), 256>>>(q, Wk, a,
        32, 256, 256, 2048, 32, 32, 256);
    // K4: fused scores + segment softmax + weighted pooling -> g_pv
    attn_kernel<<<S_NUM, 256>>>(E);
    // K5a: ps[:,hb] = pv[:,h,:] @ Wv[:,hb]  (batched over heads, N=32)
    gemm_t<32, false><<<dim3(1, 128, 8), 256>>>(pv, Wv, ps,
        256, 2048, 256, 256, 256, 32, 32);
    // K5b: out = ps @ Wo
    gemm_t<64, false><<<dim3(4, 128, 1), 256>>>(ps, Wo, out,
        256, 256, 256, 256, 0, 0, 0);
}